// round 5
// baseline (speedup 1.0000x reference)
#include <cuda_runtime.h>
#include <stdint.h>

// ---------------------------------------------------------------------------
// JAX threefry2x32 (exact): 20 rounds, key schedule ks2 = k0^k1^0x1BD11BDA
// ---------------------------------------------------------------------------
__host__ __device__ __forceinline__ void threefry2x32(
    uint32_t k0, uint32_t k1, uint32_t x0, uint32_t x1,
    uint32_t& o0, uint32_t& o1)
{
    uint32_t ks2 = k0 ^ k1 ^ 0x1BD11BDAu;
    x0 += k0; x1 += k1;
#define TF_RND(R) { x0 += x1; x1 = (x1 << (R)) | (x1 >> (32 - (R))); x1 ^= x0; }
    TF_RND(13) TF_RND(15) TF_RND(26) TF_RND(6)   x0 += k1;  x1 += ks2 + 1u;
    TF_RND(17) TF_RND(29) TF_RND(16) TF_RND(24)  x0 += ks2; x1 += k0  + 2u;
    TF_RND(13) TF_RND(15) TF_RND(26) TF_RND(6)   x0 += k0;  x1 += k1  + 3u;
    TF_RND(17) TF_RND(29) TF_RND(16) TF_RND(24)  x0 += k1;  x1 += ks2 + 4u;
    TF_RND(13) TF_RND(15) TF_RND(26) TF_RND(6)   x0 += ks2; x1 += k0  + 5u;
#undef TF_RND
    o0 = x0; o1 = x1;
}

// Partitionable-threefry 32-bit word for flat element index e:
// counter (hi=0, lo=e); fold the two outputs with XOR.
__device__ __forceinline__ uint32_t tf_bits32(uint32_t k0, uint32_t k1, uint32_t e) {
    uint32_t o0, o1;
    threefry2x32(k0, k1, 0u, e, o0, o1);
    return o0 ^ o1;
}

__device__ __forceinline__ float tf_uniform(uint32_t bits) {
    return __uint_as_float((bits >> 9) | 0x3F800000u) - 1.0f;
}

// ---------------------------------------------------------------------------
// Fused Linear (y = x @ W^T + b) + inverted dropout (keep=0.8, scale 1.25).
//
// Block tile: 128 rows x 128 cols, 256 threads, 8x8 micro-tile.
// Smem tiles are K-MAJOR (As[k][row], Bs[k][n], stride 132) so the inner
// loop reads are LDS.128 (A reads warp-broadcast) -- the R4 kernel was
// LDS-crossbar bound on strided scalar A reads.
// Register double-buffer over k-tiles: LDG next -> compute cur -> STS next,
// one __syncthreads per k-tile.
// ---------------------------------------------------------------------------
#define TKK   32
#define LDS_  132                 // stage row stride (floats); 528B = 16B-mult
#define STAGE (TKK * LDS_)        // 4224 floats per tile stage

__global__ __launch_bounds__(256, 2) void hetero_linear_dropout_kernel(
    const float* __restrict__ x, const float* __restrict__ W,
    const float* __restrict__ bias, float* __restrict__ out,
    int N, int C, uint32_t k0, uint32_t k1)
{
    extern __shared__ float sm[];
    float* AsBase = sm;               // [2][32][132]
    float* BsBase = sm + 2 * STAGE;   // [2][32][132]

    const int tid  = threadIdx.x;
    const int tx   = tid & 15;        // col group: cols tx*8 .. +7
    const int ty   = tid >> 4;        // row group: rows ty*8 .. +7
    const int base = blockIdx.x * 128;

    // per-thread load coords (4 float4 per tile for A and for B)
    const int lrow = tid >> 3;        // 0..31 (+32*i)
    const int lkq  = tid & 7;         // float4 group within 32-k tile

    float acc[8][8];
#pragma unroll
    for (int i = 0; i < 8; i++)
#pragma unroll
        for (int j = 0; j < 8; j++) acc[i][j] = 0.0f;

    const int ksteps = C >> 5;

    float4 pa[4], pb[4];

    // ---- fetch k-tile 0 into registers ----
#pragma unroll
    for (int i = 0; i < 4; i++) {
        int row = lrow + 32 * i;
        int gr  = base + row;
        pa[i] = make_float4(0.f, 0.f, 0.f, 0.f);
        if (gr < N) pa[i] = *(const float4*)(x + (long)gr * C + lkq * 4);
        pb[i] = *(const float4*)(W + (long)row * C + lkq * 4);
    }
    // ---- stash into stage 0 ----
#pragma unroll
    for (int i = 0; i < 4; i++) {
        int row = lrow + 32 * i;
        float* da = AsBase + (lkq * 4) * LDS_ + row;
        da[0] = pa[i].x; da[LDS_] = pa[i].y; da[2*LDS_] = pa[i].z; da[3*LDS_] = pa[i].w;
        float* db = BsBase + (lkq * 4) * LDS_ + row;
        db[0] = pb[i].x; db[LDS_] = pb[i].y; db[2*LDS_] = pb[i].z; db[3*LDS_] = pb[i].w;
    }
    __syncthreads();

    for (int ks = 0; ks < ksteps; ks++) {
        const int cur = ks & 1;
        const bool hn = (ks + 1) < ksteps;

        if (hn) {
            const int kbase = (ks + 1) << 5;
#pragma unroll
            for (int i = 0; i < 4; i++) {
                int row = lrow + 32 * i;
                int gr  = base + row;
                pa[i] = make_float4(0.f, 0.f, 0.f, 0.f);
                if (gr < N) pa[i] = *(const float4*)(x + (long)gr * C + kbase + lkq * 4);
                pb[i] = *(const float4*)(W + (long)row * C + kbase + lkq * 4);
            }
        }

        // ---- compute current stage ----
        const float* Ak = AsBase + cur * STAGE;
        const float* Bk = BsBase + cur * STAGE;
#pragma unroll
        for (int kk = 0; kk < TKK; kk++) {
            float4 a0 = *(const float4*)(Ak + kk * LDS_ + ty * 8);
            float4 a1 = *(const float4*)(Ak + kk * LDS_ + ty * 8 + 4);
            float4 b0 = *(const float4*)(Bk + kk * LDS_ + tx * 8);
            float4 b1 = *(const float4*)(Bk + kk * LDS_ + tx * 8 + 4);
            float a[8] = {a0.x, a0.y, a0.z, a0.w, a1.x, a1.y, a1.z, a1.w};
            float b[8] = {b0.x, b0.y, b0.z, b0.w, b1.x, b1.y, b1.z, b1.w};
#pragma unroll
            for (int i = 0; i < 8; i++)
#pragma unroll
                for (int j = 0; j < 8; j++)
                    acc[i][j] = fmaf(a[i], b[j], acc[i][j]);
        }

        if (hn) {
            const int nxt = cur ^ 1;
#pragma unroll
            for (int i = 0; i < 4; i++) {
                int row = lrow + 32 * i;
                float* da = AsBase + nxt * STAGE + (lkq * 4) * LDS_ + row;
                da[0] = pa[i].x; da[LDS_] = pa[i].y; da[2*LDS_] = pa[i].z; da[3*LDS_] = pa[i].w;
                float* db = BsBase + nxt * STAGE + (lkq * 4) * LDS_ + row;
                db[0] = pb[i].x; db[LDS_] = pb[i].y; db[2*LDS_] = pb[i].z; db[3*LDS_] = pb[i].w;
            }
            __syncthreads();
        }
    }

    // ---- epilogue: bias + partitionable-threefry dropout ----
    float bc[8];
    {
        float4 b0 = *(const float4*)(bias + tx * 8);
        float4 b1 = *(const float4*)(bias + tx * 8 + 4);
        bc[0]=b0.x; bc[1]=b0.y; bc[2]=b0.z; bc[3]=b0.w;
        bc[4]=b1.x; bc[5]=b1.y; bc[6]=b1.z; bc[7]=b1.w;
    }

#pragma unroll
    for (int i = 0; i < 8; i++) {
        int row = base + ty * 8 + i;
        if (row < N) {
            uint32_t ebase = (uint32_t)row * 128u + (uint32_t)(tx * 8);
            float4 v0, v1;
            float* p0 = &v0.x;
            float* p1 = &v1.x;
#pragma unroll
            for (int j = 0; j < 4; j++) {
                float y = acc[i][j] + bc[j];
                uint32_t bits = tf_bits32(k0, k1, ebase + (uint32_t)j);
                p0[j] = (tf_uniform(bits) < 0.8f) ? y * 1.25f : 0.0f;
            }
#pragma unroll
            for (int j = 0; j < 4; j++) {
                float y = acc[i][4 + j] + bc[4 + j];
                uint32_t bits = tf_bits32(k0, k1, ebase + 4u + (uint32_t)j);
                p1[j] = (tf_uniform(bits) < 0.8f) ? y * 1.25f : 0.0f;
            }
            float* op = out + (size_t)row * 128 + tx * 8;
            *(float4*)op       = v0;
            *(float4*)(op + 4) = v1;
        }
    }
}

// ---------------------------------------------------------------------------
// Launch. Inputs interleaved per type (x_t, W_t, b_t) x 8; detect layout.
// ---------------------------------------------------------------------------
static const int C_TAB[8] = {128, 256, 64, 128, 192, 96, 160, 128};
static const int SMEM_BYTES = 4 * STAGE * 4;   // 67584

extern "C" void kernel_launch(void* const* d_in, const int* in_sizes, int n_in,
                              void* d_out, int out_size)
{
    (void)n_in; (void)out_size;
    const bool interleaved = (in_sizes[1] == 128 * C_TAB[0]);

    cudaFuncSetAttribute(hetero_linear_dropout_kernel,
                         cudaFuncAttributeMaxDynamicSharedMemorySize, SMEM_BYTES);

    size_t off = 0;
    for (int t = 0; t < 8; t++) {
        const int C = C_TAB[t];
        const int xi = interleaved ? (3 * t)     : t;
        const int wi = interleaved ? (3 * t + 1) : (8 + t);
        const int bi = interleaved ? (3 * t + 2) : (16 + t);
        const int N  = in_sizes[xi] / C;

        uint32_t fk0, fk1;
        threefry2x32(0u, 42u, 0u, (uint32_t)t, fk0, fk1);

        const float* x = (const float*)d_in[xi];
        const float* W = (const float*)d_in[wi];
        const float* b = (const float*)d_in[bi];
        float* out = (float*)d_out + off;

        int grid = (N + 127) / 128;
        hetero_linear_dropout_kernel<<<grid, 256, SMEM_BYTES>>>(
            x, W, b, out, N, C, fk0, fk1);

        off += (size_t)N * 128;
    }
}

// round 7
// speedup vs baseline: 1.6142x; 1.6142x over previous
#include <cuda_runtime.h>
#include <cuda_bf16.h>
#include <stdint.h>

// ===========================================================================
// JAX threefry2x32 (exact)
// ===========================================================================
__host__ __device__ __forceinline__ void threefry2x32(
    uint32_t k0, uint32_t k1, uint32_t x0, uint32_t x1,
    uint32_t& o0, uint32_t& o1)
{
    uint32_t ks2 = k0 ^ k1 ^ 0x1BD11BDAu;
    x0 += k0; x1 += k1;
#define TF_RND(R) { x0 += x1; x1 = (x1 << (R)) | (x1 >> (32 - (R))); x1 ^= x0; }
    TF_RND(13) TF_RND(15) TF_RND(26) TF_RND(6)   x0 += k1;  x1 += ks2 + 1u;
    TF_RND(17) TF_RND(29) TF_RND(16) TF_RND(24)  x0 += ks2; x1 += k0  + 2u;
    TF_RND(13) TF_RND(15) TF_RND(26) TF_RND(6)   x0 += k0;  x1 += k1  + 3u;
    TF_RND(17) TF_RND(29) TF_RND(16) TF_RND(24)  x0 += k1;  x1 += ks2 + 4u;
    TF_RND(13) TF_RND(15) TF_RND(26) TF_RND(6)   x0 += ks2; x1 += k0  + 5u;
#undef TF_RND
    o0 = x0; o1 = x1;
}

// Partitionable-threefry 32-bit word for flat element index e (<2^32):
// counter (hi=0, lo=e); XOR-fold the two outputs. (Bit-exact vs JAX: R4/R5.)
__device__ __forceinline__ uint32_t tf_bits32(uint32_t k0, uint32_t k1, uint32_t e) {
    uint32_t o0, o1;
    threefry2x32(k0, k1, 0u, e, o0, o1);
    return o0 ^ o1;
}
__device__ __forceinline__ float tf_uniform(uint32_t bits) {
    return __uint_as_float((bits >> 9) | 0x3F800000u) - 1.0f;
}

// ===========================================================================
// Tensor-core primitives (baseline PTX, valid for compute_103 non-'a')
// ===========================================================================
__device__ __forceinline__ uint32_t smem_u32(const void* p) {
    uint32_t a;
    asm("{ .reg .u64 t; cvta.to.shared.u64 t, %1; cvt.u32.u64 %0, t; }"
        : "=r"(a) : "l"(p));
    return a;
}

__device__ __forceinline__ void ldm4(uint32_t addr,
    uint32_t& r0, uint32_t& r1, uint32_t& r2, uint32_t& r3)
{
    asm volatile("ldmatrix.sync.aligned.m8n8.x4.shared.b16 {%0,%1,%2,%3}, [%4];"
                 : "=r"(r0), "=r"(r1), "=r"(r2), "=r"(r3) : "r"(addr));
}

__device__ __forceinline__ void mma16816(float* d,
    uint32_t a0, uint32_t a1, uint32_t a2, uint32_t a3,
    uint32_t b0, uint32_t b1)
{
    asm volatile(
        "mma.sync.aligned.m16n8k16.row.col.f32.bf16.bf16.f32 "
        "{%0,%1,%2,%3}, {%4,%5,%6,%7}, {%8,%9}, {%0,%1,%2,%3};"
        : "+f"(d[0]), "+f"(d[1]), "+f"(d[2]), "+f"(d[3])
        : "r"(a0), "r"(a1), "r"(a2), "r"(a3), "r"(b0), "r"(b1));
}

// pack 4 floats into 4 hi-bf16 + 4 lo-bf16 (uint2 each)
__device__ __forceinline__ void split4(float4 v, uint2& hi, uint2& lo) {
    __nv_bfloat16 h0 = __float2bfloat16(v.x);
    __nv_bfloat16 h1 = __float2bfloat16(v.y);
    __nv_bfloat16 h2 = __float2bfloat16(v.z);
    __nv_bfloat16 h3 = __float2bfloat16(v.w);
    __nv_bfloat16 l0 = __float2bfloat16(v.x - __bfloat162float(h0));
    __nv_bfloat16 l1 = __float2bfloat16(v.y - __bfloat162float(h1));
    __nv_bfloat16 l2 = __float2bfloat16(v.z - __bfloat162float(h2));
    __nv_bfloat16 l3 = __float2bfloat16(v.w - __bfloat162float(h3));
    hi.x = (uint32_t)__bfloat16_as_ushort(h0) | ((uint32_t)__bfloat16_as_ushort(h1) << 16);
    hi.y = (uint32_t)__bfloat16_as_ushort(h2) | ((uint32_t)__bfloat16_as_ushort(h3) << 16);
    lo.x = (uint32_t)__bfloat16_as_ushort(l0) | ((uint32_t)__bfloat16_as_ushort(l1) << 16);
    lo.y = (uint32_t)__bfloat16_as_ushort(l2) | ((uint32_t)__bfloat16_as_ushort(l3) << 16);
}

// ===========================================================================
// Fused: y = x @ W^T + b, then inverted dropout (keep=0.8), bf16 hi/lo split
// GEMM on mma.sync tensor cores (HH + LH + HL products).
//
// Block: 128 rows x 128 cols, 256 threads = 8 warps, warp tile 32x64.
// Smem: 4 tiles [128 rows][40 bf16] (32 k + 8 pad -> 80B row stride,
// conflict-free for ldmatrix). K-tile = 32.
// ===========================================================================
#define RS 40   // row stride in bf16 elems (80 bytes)

__global__ __launch_bounds__(256, 2) void fused_gemm_dropout(
    const float* __restrict__ x, const float* __restrict__ W,
    const float* __restrict__ bias, float* __restrict__ out,
    int N, int C, uint32_t k0, uint32_t k1)
{
    __shared__ __align__(16) uint16_t Ah[128 * RS], Al[128 * RS];
    __shared__ __align__(16) uint16_t Bh[128 * RS], Bl[128 * RS];

    const int tid  = threadIdx.x;
    const int lane = tid & 31;
    const int warp = tid >> 5;
    const int wm   = warp & 3;        // m offset = wm*32
    const int wn   = warp >> 2;       // n offset = wn*64
    const int base = blockIdx.x * 128;

    const uint32_t uAh = smem_u32(Ah), uAl = smem_u32(Al);
    const uint32_t uBh = smem_u32(Bh), uBl = smem_u32(Bl);

    // ldmatrix lane address components
    const int r16  = lane & 15;
    const int hc16 = (lane >> 4) << 4;   // 0 or 16 bytes (k half)

    float acc[2][8][4];
#pragma unroll
    for (int i = 0; i < 2; i++)
#pragma unroll
        for (int j = 0; j < 8; j++)
#pragma unroll
            for (int q = 0; q < 4; q++) acc[i][j][q] = 0.0f;

    for (int kt = 0; kt < C; kt += 32) {
        // ---- load fp32, split to bf16 hi/lo, store to smem ----
#pragma unroll
        for (int it = 0; it < 4; it++) {
            int idx = tid + it * 256;     // 0..1023
            int row = idx >> 3;
            int q   = idx & 7;            // float4 group (4 k)
            int soff = row * RS + q * 4;  // bf16 elems

            int gr = base + row;
            float4 va = make_float4(0.f, 0.f, 0.f, 0.f);
            if (gr < N) va = *(const float4*)(x + (long)gr * C + kt + q * 4);
            uint2 hi, lo;
            split4(va, hi, lo);
            *(uint2*)(Ah + soff) = hi;
            *(uint2*)(Al + soff) = lo;

            float4 vw = *(const float4*)(W + (long)row * C + kt + q * 4);
            split4(vw, hi, lo);
            *(uint2*)(Bh + soff) = hi;
            *(uint2*)(Bl + soff) = lo;
        }
        __syncthreads();

#pragma unroll
        for (int c = 0; c < 2; c++) {
            const int coff = c * 32 + hc16;   // byte offset in row

            // A hi frags (2 m-atoms)
            uint32_t ah[2][4];
#pragma unroll
            for (int am = 0; am < 2; am++)
                ldm4(uAh + (uint32_t)((wm * 32 + am * 16 + r16) * 80 + coff),
                     ah[am][0], ah[am][1], ah[am][2], ah[am][3]);

            // B hi frags (4 pair-groups covering 8 n-atoms)
            uint32_t b[4][4];
#pragma unroll
            for (int p = 0; p < 4; p++)
                ldm4(uBh + (uint32_t)((wn * 64 + p * 16 + r16) * 80 + coff),
                     b[p][0], b[p][1], b[p][2], b[p][3]);

            // HH
#pragma unroll
            for (int am = 0; am < 2; am++)
#pragma unroll
                for (int p = 0; p < 4; p++) {
                    mma16816(acc[am][2 * p],     ah[am][0], ah[am][1], ah[am][2], ah[am][3], b[p][0], b[p][2]);
                    mma16816(acc[am][2 * p + 1], ah[am][0], ah[am][1], ah[am][2], ah[am][3], b[p][1], b[p][3]);
                }

            // A lo frags, LH
            uint32_t al[2][4];
#pragma unroll
            for (int am = 0; am < 2; am++)
                ldm4(uAl + (uint32_t)((wm * 32 + am * 16 + r16) * 80 + coff),
                     al[am][0], al[am][1], al[am][2], al[am][3]);
#pragma unroll
            for (int am = 0; am < 2; am++)
#pragma unroll
                for (int p = 0; p < 4; p++) {
                    mma16816(acc[am][2 * p],     al[am][0], al[am][1], al[am][2], al[am][3], b[p][0], b[p][2]);
                    mma16816(acc[am][2 * p + 1], al[am][0], al[am][1], al[am][2], al[am][3], b[p][1], b[p][3]);
                }

            // B lo frags (overwrite b), HL
#pragma unroll
            for (int p = 0; p < 4; p++)
                ldm4(uBl + (uint32_t)((wn * 64 + p * 16 + r16) * 80 + coff),
                     b[p][0], b[p][1], b[p][2], b[p][3]);
#pragma unroll
            for (int am = 0; am < 2; am++)
#pragma unroll
                for (int p = 0; p < 4; p++) {
                    mma16816(acc[am][2 * p],     ah[am][0], ah[am][1], ah[am][2], ah[am][3], b[p][0], b[p][2]);
                    mma16816(acc[am][2 * p + 1], ah[am][0], ah[am][1], ah[am][2], ah[am][3], b[p][1], b[p][3]);
                }
        }
        __syncthreads();
    }

    // ---- epilogue: bias + partitionable-threefry dropout, float2 stores ----
    const int colq = (lane & 3) * 2;     // col pair within n-atom
    const int rowq = lane >> 2;          // row within half-atom
#pragma unroll
    for (int am = 0; am < 2; am++) {
        int row0 = base + wm * 32 + am * 16 + rowq;
#pragma unroll
        for (int an = 0; an < 8; an++) {
            int col = wn * 64 + an * 8 + colq;
            float b0 = __ldg(bias + col);
            float b1 = __ldg(bias + col + 1);
            // regs d0,d1 -> (row0, col/col+1); d2,d3 -> (row0+8, ...)
            if (row0 < N) {
                uint32_t e = (uint32_t)row0 * 128u + (uint32_t)col;
                float y0 = acc[am][an][0] + b0;
                float y1 = acc[am][an][1] + b1;
                float2 v;
                v.x = (tf_uniform(tf_bits32(k0, k1, e))      < 0.8f) ? y0 * 1.25f : 0.0f;
                v.y = (tf_uniform(tf_bits32(k0, k1, e + 1u)) < 0.8f) ? y1 * 1.25f : 0.0f;
                *(float2*)(out + (size_t)row0 * 128 + col) = v;
            }
            int row1 = row0 + 8;
            if (row1 < N) {
                uint32_t e = (uint32_t)row1 * 128u + (uint32_t)col;
                float y0 = acc[am][an][2] + b0;
                float y1 = acc[am][an][3] + b1;
                float2 v;
                v.x = (tf_uniform(tf_bits32(k0, k1, e))      < 0.8f) ? y0 * 1.25f : 0.0f;
                v.y = (tf_uniform(tf_bits32(k0, k1, e + 1u)) < 0.8f) ? y1 * 1.25f : 0.0f;
                *(float2*)(out + (size_t)row1 * 128 + col) = v;
            }
        }
    }
}

// ===========================================================================
// Launch: 8 fused kernels. Inputs interleaved (x_t, W_t, b_t) x 8; detect.
// ===========================================================================
static const int C_TAB[8] = {128, 256, 64, 128, 192, 96, 160, 128};

extern "C" void kernel_launch(void* const* d_in, const int* in_sizes, int n_in,
                              void* d_out, int out_size)
{
    (void)n_in; (void)out_size;
    const bool interleaved = (in_sizes[1] == 128 * C_TAB[0]);

    size_t off = 0;
    for (int t = 0; t < 8; t++) {
        const int C = C_TAB[t];
        const int xi = interleaved ? (3 * t)     : t;
        const int wi = interleaved ? (3 * t + 1) : (8 + t);
        const int bi = interleaved ? (3 * t + 2) : (16 + t);
        const int N  = in_sizes[xi] / C;

        uint32_t fk0, fk1;
        threefry2x32(0u, 42u, 0u, (uint32_t)t, fk0, fk1);

        const float* x = (const float*)d_in[xi];
        const float* W = (const float*)d_in[wi];
        const float* b = (const float*)d_in[bi];
        float* out = (float*)d_out + off;

        int grid = (N + 127) / 128;
        fused_gemm_dropout<<<grid, 256>>>(x, W, b, out, N, C, fk0, fk1);

        off += (size_t)N * 128;
    }
}